// round 6
// baseline (speedup 1.0000x reference)
#include <cuda_runtime.h>
#include <cuda_bf16.h>
#include <cstdint>

// 3D Haar DWT, x: (B=2, C=32, D=64, H=128, W=128) fp32
// out: low (2,32,32,64,64) then highs (2,32,7,32,64,64), packed.
//
// R6: fully staged. CTA tile = (bc, d, 16 out-h, 64 out-w).
//  Phase 1: read 2 contiguous 16KB input slices (thread-linear LDG.128) -> smem
//  Phase 2: Haar butterfly from smem into registers
//  Phase 3: outputs -> smem (reused buffer)
//  Phase 4: each warp drains one subband as a contiguous 4KB burst.

#define C_HAAR 0.35355339059327373f  // 1/(2*sqrt(2))

#define ROW_STRIDE 132               // 128 + 4 pad floats (528B, 16B-aligned)
#define SLICE_FLOATS (32 * ROW_STRIDE)   // 4224

__global__ __launch_bounds__(256) void dwt3d_haar_kernel(
    const float* __restrict__ x, float* __restrict__ out)
{
    __shared__ float sm[2 * SLICE_FLOATS];  // 8448 floats = 33KB (reused for out: 8192)

    unsigned t = threadIdx.x;
    unsigned bid = blockIdx.x;            // 8192 blocks
    unsigned hblk = bid & 3u;             // h block (0..3): 16 output rows
    unsigned d    = (bid >> 2) & 31u;     // output d
    unsigned bc   = bid >> 7;             // b*C + c

    // ---- Phase 1: contiguous loads. Each slice i: 16KB at
    //      (bc*64 + 2d+i)*16384 + hblk*4096
#pragma unroll
    for (int i = 0; i < 2; i++) {
        const float4* src = reinterpret_cast<const float4*>(
            x + ((size_t)bc << 20) + (((size_t)(d << 1) + i) << 14) + ((size_t)hblk << 12));
#pragma unroll
        for (int k = 0; k < 4; k++) {
            unsigned g = t + k * 256u;          // float4 index 0..1023
            float4 v = __ldcs(src + g);
            unsigned row = g >> 5, col = g & 31u;
            *reinterpret_cast<float4*>(&sm[i * SLICE_FLOATS + row * ROW_STRIDE + col * 4]) = v;
        }
    }
    __syncthreads();

    // ---- Phase 2: butterfly from smem into registers
    unsigned wg = t & 15u;                // 4 output w per thread
    unsigned hl = t >> 4;                 // local out h (0..15)

    float4 r[4][2];
#pragma unroll
    for (int i = 0; i < 2; i++) {
#pragma unroll
        for (int j = 0; j < 2; j++) {
            const float4* p = reinterpret_cast<const float4*>(
                &sm[i * SLICE_FLOATS + ((hl << 1) + j) * ROW_STRIDE + (wg << 3)]);
            r[i * 2 + j][0] = p[0];
            r[i * 2 + j][1] = p[1];
        }
    }

    float o[8][4];
#pragma unroll
    for (int m = 0; m < 4; m++) {
        float ka[2][2], kb[2][2];
#pragma unroll
        for (int i = 0; i < 2; i++) {
#pragma unroll
            for (int j = 0; j < 2; j++) {
                float4 q = r[i * 2 + j][m >> 1];
                float v0 = (m & 1) ? q.z : q.x;
                float v1 = (m & 1) ? q.w : q.y;
                ka[i][j] = v0 + v1;
                kb[i][j] = v0 - v1;
            }
        }
        float tt[2][2][2];
#pragma unroll
        for (int i = 0; i < 2; i++) {
            tt[0][0][i] = ka[i][0] + ka[i][1];
            tt[0][1][i] = ka[i][0] - ka[i][1];
            tt[1][0][i] = kb[i][0] + kb[i][1];
            tt[1][1][i] = kb[i][0] - kb[i][1];
        }
#pragma unroll
        for (int y = 0; y < 2; y++) {
#pragma unroll
            for (int xk = 0; xk < 2; xk++) {
                o[0 * 4 + y * 2 + xk][m] = C_HAAR * (tt[xk][y][0] + tt[xk][y][1]);
                o[1 * 4 + y * 2 + xk][m] = C_HAAR * (tt[xk][y][0] - tt[xk][y][1]);
            }
        }
    }
    __syncthreads();

    // ---- Phase 3: outputs -> smem (reuse buffer): [s][hl*64 + wg*4]
    unsigned sm_pos = (hl << 6) + (wg << 2);
#pragma unroll
    for (int s = 0; s < 8; s++) {
        float4 v = make_float4(o[s][0], o[s][1], o[s][2], o[s][3]);
        *reinterpret_cast<float4*>(&sm[s * 1024 + sm_pos]) = v;
    }
    __syncthreads();

    // ---- Phase 4: warp w drains subband w as a 4KB contiguous burst
    unsigned w = t >> 5;    // warp id = subband
    unsigned l = t & 31u;   // lane

    unsigned tile = (d << 12) + (hblk << 10);  // d*4096 + hblk*1024
    size_t obase;
    if (w == 0) {
        obase = ((size_t)bc << 17) + tile;                                 // low
    } else {
        obase = 8388608u + ((size_t)(bc * 7u + (w - 1)) << 17) + tile;     // highs
    }

    const float* src = &sm[w * 1024];
#pragma unroll
    for (int c = 0; c < 8; c++) {
        unsigned idx = (c << 7) + (l << 2);  // chunk*128 + lane*4
        float4 v = *reinterpret_cast<const float4*>(src + idx);
        __stcs(reinterpret_cast<float4*>(out + obase + idx), v);
    }
}

extern "C" void kernel_launch(void* const* d_in, const int* in_sizes, int n_in,
                              void* d_out, int out_size)
{
    const float* x = (const float*)d_in[0];
    float* out = (float*)d_out;
    dwt3d_haar_kernel<<<8192, 256>>>(x, out);
}

// round 7
// speedup vs baseline: 1.0444x; 1.0444x over previous
#include <cuda_runtime.h>
#include <cuda_bf16.h>
#include <cstdint>

// 3D Haar DWT, x: (B=2, C=32, D=64, H=128, W=128) fp32
// out: low (2,32,32,64,64) then highs (2,32,7,32,64,64), packed.
//
// R7: R2 structure (direct float4 + streaming hints, best measured) in a
// persistent grid-stride launch: 1184 CTAs (148 SMs x 8), each looping over
// work items -> no CTA churn, continuously fed LDG pipeline.

#define C_HAAR 0.35355339059327373f  // 1/(2*sqrt(2))

#define NWORK (2097152u)     // 64(bc)*32(d)*64(h)*16(wg)
#define NTHREADS (1184u * 256u)

__global__ __launch_bounds__(256) void dwt3d_haar_kernel(
    const float* __restrict__ x, float* __restrict__ out)
{
    unsigned tid0 = blockIdx.x * 256u + threadIdx.x;

    for (unsigned tid = tid0; tid < NWORK; tid += NTHREADS) {
        unsigned wg = tid & 15u;          // w-group: 4 output w per group
        unsigned h  = (tid >> 4) & 63u;   // output h (0..63)
        unsigned d  = (tid >> 10) & 31u;  // output d (0..31)
        unsigned bc = tid >> 15;          // b*C + c (0..63)

        // input: ((bc)*64 + 2d+i)*16384 + (2h+j)*128 + 8*wg
        size_t in_base = ((size_t)bc << 20)
                       + ((size_t)d << 15)
                       + ((size_t)h << 8)
                       + (wg << 3);

        const float4* p00 = reinterpret_cast<const float4*>(x + in_base);
        const float4* p01 = reinterpret_cast<const float4*>(x + in_base + 128);
        const float4* p10 = reinterpret_cast<const float4*>(x + in_base + 16384);
        const float4* p11 = reinterpret_cast<const float4*>(x + in_base + 16384 + 128);

        // Front-batch all 8 LDG.128 (streaming)
        float4 r00a = __ldcs(p00), r00b = __ldcs(p00 + 1);
        float4 r01a = __ldcs(p01), r01b = __ldcs(p01 + 1);
        float4 r10a = __ldcs(p10), r10b = __ldcs(p10 + 1);
        float4 r11a = __ldcs(p11), r11b = __ldcs(p11 + 1);

        float4 r[4][2] = {{r00a, r00b}, {r01a, r01b}, {r10a, r10b}, {r11a, r11b}};

        // o[s][m]: subband s (i*4 + j*2 + k bits, 0=low-pass), site m (0..3)
        float o[8][4];

#pragma unroll
        for (int m = 0; m < 4; m++) {
            float ka[2][2], kb[2][2];  // k-stage sum/diff
#pragma unroll
            for (int i = 0; i < 2; i++) {
#pragma unroll
                for (int j = 0; j < 2; j++) {
                    float4 q = r[i * 2 + j][m >> 1];
                    float v0 = (m & 1) ? q.z : q.x;
                    float v1 = (m & 1) ? q.w : q.y;
                    ka[i][j] = v0 + v1;
                    kb[i][j] = v0 - v1;
                }
            }
            float t[2][2][2];  // t[x][y][i]: after j-stage
#pragma unroll
            for (int i = 0; i < 2; i++) {
                t[0][0][i] = ka[i][0] + ka[i][1];
                t[0][1][i] = ka[i][0] - ka[i][1];
                t[1][0][i] = kb[i][0] + kb[i][1];
                t[1][1][i] = kb[i][0] - kb[i][1];
            }
#pragma unroll
            for (int y = 0; y < 2; y++) {
#pragma unroll
                for (int xk = 0; xk < 2; xk++) {
                    o[0 * 4 + y * 2 + xk][m] = C_HAAR * (t[xk][y][0] + t[xk][y][1]);
                    o[1 * 4 + y * 2 + xk][m] = C_HAAR * (t[xk][y][0] - t[xk][y][1]);
                }
            }
        }

        // Output addresses: spatial = d*4096 + h*64 + 4*wg
        unsigned spatial = (d << 12) + (h << 6) + (wg << 2);

        // low: out[bc*131072 + spatial]
        {
            float4 v = make_float4(o[0][0], o[0][1], o[0][2], o[0][3]);
            __stcs(reinterpret_cast<float4*>(out + ((size_t)bc << 17) + spatial), v);
        }
        // highs: out[8388608 + (bc*7 + (s-1))*131072 + spatial]
#pragma unroll
        for (int s = 1; s < 8; s++) {
            float4 v = make_float4(o[s][0], o[s][1], o[s][2], o[s][3]);
            size_t off = 8388608u + ((size_t)(bc * 7u + (unsigned)(s - 1)) << 17) + spatial;
            __stcs(reinterpret_cast<float4*>(out + off), v);
        }
    }
}

extern "C" void kernel_launch(void* const* d_in, const int* in_sizes, int n_in,
                              void* d_out, int out_size)
{
    const float* x = (const float*)d_in[0];
    float* out = (float*)d_out;
    dwt3d_haar_kernel<<<1184, 256>>>(x, out);
}

// round 8
// speedup vs baseline: 1.0737x; 1.0281x over previous
#include <cuda_runtime.h>
#include <cuda_bf16.h>
#include <cstdint>

// 3D Haar DWT, x: (B=2, C=32, D=64, H=128, W=128) fp32
// out: low (2,32,32,64,64) then highs (2,32,7,32,64,64), packed.
//
// CHAMPION (R2 structure): direct per-thread float4 streaming with
// evict-first cache hints. Measured best across 7 structural variants:
// 75.3us kernel / 82.0us harness, DRAM 81.1% (6.43 TB/s). Traffic is
// minimal (512MB); ~81% DRAM is the mixed-R/W controller ceiling.

#define C_HAAR 0.35355339059327373f  // 1/(2*sqrt(2))

__global__ __launch_bounds__(256) void dwt3d_haar_kernel(
    const float* __restrict__ x, float* __restrict__ out)
{
    // total threads = 2,097,152 = 64(bc) * 32(d) * 64(h) * 16(wg)
    unsigned tid = blockIdx.x * 256u + threadIdx.x;
    unsigned wg = tid & 15u;          // w-group: 4 output w per group
    unsigned h  = (tid >> 4) & 63u;   // output h (0..63)
    unsigned d  = (tid >> 10) & 31u;  // output d (0..31)
    unsigned bc = tid >> 15;          // b*C + c (0..63)

    // input: ((bc)*64 + 2d+i)*16384 + (2h+j)*128 + 8*wg
    size_t in_base = ((size_t)bc << 20)
                   + ((size_t)d << 15)
                   + ((size_t)h << 8)
                   + (wg << 3);

    // Load 4 rows (i,j in {0,1}^2), 8 contiguous floats each (2x LDG.128),
    // streaming (evict-first) — no reuse anywhere.
    float4 r[4][2];
#pragma unroll
    for (int i = 0; i < 2; i++) {
#pragma unroll
        for (int j = 0; j < 2; j++) {
            const float4* p = reinterpret_cast<const float4*>(
                x + in_base + (size_t)i * 16384 + (size_t)j * 128);
            r[i * 2 + j][0] = __ldcs(p);
            r[i * 2 + j][1] = __ldcs(p + 1);
        }
    }

    // o[s][m]: subband s (i*4 + j*2 + k bits, 0=low-pass), output site m (0..3)
    float o[8][4];

#pragma unroll
    for (int m = 0; m < 4; m++) {
        float ka[2][2], kb[2][2];  // k-stage sum/diff
#pragma unroll
        for (int i = 0; i < 2; i++) {
#pragma unroll
            for (int j = 0; j < 2; j++) {
                float4 q = r[i * 2 + j][m >> 1];
                float v0 = (m & 1) ? q.z : q.x;
                float v1 = (m & 1) ? q.w : q.y;
                ka[i][j] = v0 + v1;
                kb[i][j] = v0 - v1;
            }
        }
        float t[2][2][2];  // t[x][y][i]: after j-stage
#pragma unroll
        for (int i = 0; i < 2; i++) {
            t[0][0][i] = ka[i][0] + ka[i][1];
            t[0][1][i] = ka[i][0] - ka[i][1];
            t[1][0][i] = kb[i][0] + kb[i][1];
            t[1][1][i] = kb[i][0] - kb[i][1];
        }
#pragma unroll
        for (int y = 0; y < 2; y++) {
#pragma unroll
            for (int xk = 0; xk < 2; xk++) {
                o[0 * 4 + y * 2 + xk][m] = C_HAAR * (t[xk][y][0] + t[xk][y][1]);
                o[1 * 4 + y * 2 + xk][m] = C_HAAR * (t[xk][y][0] - t[xk][y][1]);
            }
        }
    }

    // Output addresses: spatial = d*4096 + h*64 + 4*wg
    unsigned spatial = (d << 12) + (h << 6) + (wg << 2);

    // low: out[bc*131072 + spatial]
    {
        float4 v = make_float4(o[0][0], o[0][1], o[0][2], o[0][3]);
        __stcs(reinterpret_cast<float4*>(out + ((size_t)bc << 17) + spatial), v);
    }
    // highs: out[8388608 + (bc*7 + (s-1))*131072 + spatial]
#pragma unroll
    for (int s = 1; s < 8; s++) {
        float4 v = make_float4(o[s][0], o[s][1], o[s][2], o[s][3]);
        size_t off = 8388608u + ((size_t)(bc * 7u + (unsigned)(s - 1)) << 17) + spatial;
        __stcs(reinterpret_cast<float4*>(out + off), v);
    }
}

extern "C" void kernel_launch(void* const* d_in, const int* in_sizes, int n_in,
                              void* d_out, int out_size)
{
    const float* x = (const float*)d_in[0];
    float* out = (float*)d_out;
    dwt3d_haar_kernel<<<8192, 256>>>(x, out);
}